// round 3
// baseline (speedup 1.0000x reference)
#include <cuda_runtime.h>
#include <cuda_bf16.h>

#define BB 16
#define LL 8400
#define NG 32
#define KK 68
#define NTOPK 13
#define EPSV 1e-9f

// flat output offsets (float32 elements), tuple order:
// labels(B,L), bboxes(B,L,4), scores(B,L,1), poses(B,L,K,3), vertices(B,L,K,3),
// rotations(B,L,3,3), gt_index(B,L)
#define O1 134400
#define O2 672000
#define O3 806400
#define O4 28224000
#define O5 55641600
#define O6 56851200

// scratch (static __device__ globals — no runtime allocation)
__device__ unsigned int g_mask[BB * LL];   // per-anchor gt bitmask (initial mask_positive)
__device__ unsigned int g_final[BB * LL];  // after multi-claim resolution
__device__ int          g_gidx[BB * LL];   // flat assigned gt index
__device__ int          g_maxm[BB * NG];   // per-gt max metric   (float bits, >=0)
__device__ int          g_maxiou[BB * NG]; // per-gt max iou      (float bits, >=0)

__device__ __forceinline__ float iou_fn(float gx1, float gy1, float gx2, float gy2,
                                        float px1, float py1, float px2, float py2) {
    float ix1 = fmaxf(gx1, px1), iy1 = fmaxf(gy1, py1);
    float ix2 = fminf(gx2, px2), iy2 = fminf(gy2, py2);
    float ov = fmaxf(ix2 - ix1, 0.f) * fmaxf(iy2 - iy1, 0.f);
    float a1 = fmaxf(gx2 - gx1, 0.f) * fmaxf(gy2 - gy1, 0.f);
    float a2 = fmaxf(px2 - px1, 0.f) * fmaxf(py2 - py1, 0.f);
    return ov / (a1 + a2 - ov + EPSV);
}

__device__ __forceinline__ bool in_gts_fn(float ax, float ay, float4 g) {
    return (ax - g.x > EPSV) && (ay - g.y > EPSV) && (g.z - ax > EPSV) && (g.w - ay > EPSV);
}

// ---------------- K0: zero scratch ----------------
__global__ void k0_zero() {
    int idx = blockIdx.x * blockDim.x + threadIdx.x;
    int stride = gridDim.x * blockDim.x;
    for (int i = idx; i < BB * LL; i += stride) g_mask[i] = 0u;
    for (int i = idx; i < BB * NG; i += stride) { g_maxm[i] = 0; g_maxiou[i] = 0; }
}

// ---------------- K1: per (b,gt) top-13 selection ----------------
// metric = score^1 * iou^6 * is_in_gts; stable tiebreak = lowest index (matches lax.top_k)
__global__ void k1_topk(const float* __restrict__ ps, const float* __restrict__ pb,
                        const float* __restrict__ ap, const float* __restrict__ gtb,
                        const float* __restrict__ pad) {
    __shared__ float sm[LL];
    __shared__ float rv[256];
    __shared__ int   ri[256];
    int b  = blockIdx.x >> 5;
    int gi = blockIdx.x & 31;
    int t  = threadIdx.x;
    int gid = b * NG + gi;
    float4 g = ((const float4*)gtb)[gid];
    float padv = pad[gid];
    const float* psb = ps + (size_t)b * LL;
    const float4* pbb = ((const float4*)pb) + (size_t)b * LL;

    for (int l = t; l < LL; l += 256) {
        float4 p = pbb[l];
        float ax = ap[2 * l], ay = ap[2 * l + 1];
        float m = 0.f;
        if (in_gts_fn(ax, ay, g)) {
            float iou = iou_fn(g.x, g.y, g.z, g.w, p.x, p.y, p.z, p.w);
            float i2 = iou * iou;
            m = psb[l] * (i2 * i2 * i2);
        }
        sm[l] = m;
    }
    __syncthreads();
    if (padv == 0.f) return;  // topk_mask == 0 -> no positives from this gt

    for (int k = 0; k < NTOPK; k++) {
        float bv = -1.f; int bi = LL;
        for (int l = t; l < LL; l += 256) {
            float v = sm[l];
            if (v > bv) { bv = v; bi = l; }  // strided ascending: first hit keeps lowest idx on ties
        }
        rv[t] = bv; ri[t] = bi;
        __syncthreads();
        for (int s = 128; s > 0; s >>= 1) {
            if (t < s) {
                float ov = rv[t + s]; int oi = ri[t + s];
                if (ov > rv[t] || (ov == rv[t] && oi < ri[t])) { rv[t] = ov; ri[t] = oi; }
            }
            __syncthreads();
        }
        if (t == 0) {
            int sel = ri[0];
            sm[sel] = -1.f;  // exclude from next rounds
            float ax = ap[2 * sel], ay = ap[2 * sel + 1];
            if (in_gts_fn(ax, ay, g))  // mask_positive = topk & in_gts & pad
                atomicOr(&g_mask[b * LL + sel], 1u << gi);
        }
        __syncthreads();
    }
}

// ---------------- K2: resolve multi-claims, per-gt maxima ----------------
__global__ void k2_resolve(const float* __restrict__ ps, const float* __restrict__ pb,
                           const float* __restrict__ gtb) {
    int b = blockIdx.y;
    int l = blockIdx.x * blockDim.x + threadIdx.x;
    __shared__ float4 sg[NG];
    if (threadIdx.x < NG) sg[threadIdx.x] = ((const float4*)gtb)[b * NG + threadIdx.x];
    __syncthreads();
    if (l >= LL) return;
    int a = b * LL + l;
    unsigned bits = g_mask[a];
    int cnt = __popc(bits);
    float4 p; float sc = 0.f;
    if (bits) { p = ((const float4*)pb)[a]; sc = ps[a]; }
    if (cnt > 1) {
        // replace column with one-hot argmax-iou over ALL gts (first-index tiebreak)
        float bv = -1.f; int bi = 0;
        #pragma unroll
        for (int i = 0; i < NG; i++) {
            float4 g = sg[i];
            float iou = iou_fn(g.x, g.y, g.z, g.w, p.x, p.y, p.z, p.w);
            if (iou > bv) { bv = iou; bi = i; }
        }
        bits = 1u << bi;
    }
    g_final[a] = bits;
    if (bits) {
        int i = __ffs(bits) - 1;
        float4 g = sg[i];
        float iou = iou_fn(g.x, g.y, g.z, g.w, p.x, p.y, p.z, p.w);
        float i2 = iou * iou;
        float m = sc * (i2 * i2 * i2);
        atomicMax(&g_maxm[b * NG + i], __float_as_int(m));     // values >= 0: int order == float order
        atomicMax(&g_maxiou[b * NG + i], __float_as_int(iou));
    }
}

// ---------------- K3: small outputs (labels, bboxes, scores, rotations, gt_index) ----------------
__global__ void k3_assign(const float* __restrict__ ps, const float* __restrict__ pb,
                          const float* __restrict__ gtb, const float* __restrict__ grot,
                          const int* __restrict__ gl, const int* __restrict__ bgp,
                          float* __restrict__ out) {
    int b = blockIdx.y;
    int l = blockIdx.x * blockDim.x + threadIdx.x;
    __shared__ float4 sg[NG];
    if (threadIdx.x < NG) sg[threadIdx.x] = ((const float4*)gtb)[b * NG + threadIdx.x];
    __syncthreads();
    if (l >= LL) return;
    int a = b * LL + l;
    unsigned bits = g_final[a];
    int i = bits ? (__ffs(bits) - 1) : 0;
    int gidx = b * NG + i;
    g_gidx[a] = gidx;

    int bg = bgp[0];
    int lbl = bits ? gl[gidx] : bg;   // gt labels are all 0 for C=1

    float score = 0.f;
    if (bits) {
        float4 g = sg[i];
        float4 p = ((const float4*)pb)[a];
        float iou = iou_fn(g.x, g.y, g.z, g.w, p.x, p.y, p.z, p.w);
        float i2 = iou * iou;
        float m = ps[a] * (i2 * i2 * i2);
        float mm = __int_as_float(g_maxm[gidx]);
        float mi = __int_as_float(g_maxiou[gidx]);
        float am = m / (mm + EPSV) * mi;
        score = (lbl == 0) ? am : 0.f;  // one_hot(lbl, C+1)[..., keep=[0]]
    }

    out[a] = (float)lbl;                       // assigned_labels
    ((float4*)(out + O1))[a] = sg[i];          // assigned_bboxes (gather regardless of positivity)
    out[O2 + a] = score;                       // assigned_scores
    const float* rs = grot + (size_t)gidx * 9; // assigned_rotations
    float* rd = out + O5 + (size_t)a * 9;
    #pragma unroll
    for (int r = 0; r < 9; r++) rd[r] = rs[r];
    out[O6 + a] = (float)gidx;                 // assigned_gt_index
}

// ---------------- K4: big gather copy (poses + vertices), float4 granularity ----------------
// 51 float4 per anchor per tensor; 102 float4 units per anchor total.
__global__ void k4_copy(const float* __restrict__ gp, const float* __restrict__ gv,
                        float* __restrict__ out) {
    size_t t = (size_t)blockIdx.x * blockDim.x + threadIdx.x;
    const size_t total = (size_t)BB * LL * 102;
    if (t >= total) return;
    size_t a = t / 102;
    int c = (int)(t - a * 102);
    size_t gidx = (size_t)g_gidx[a];
    const float4* P = (const float4*)gp;
    const float4* V = (const float4*)gv;
    float4* OP = (float4*)(out + O3);
    float4* OV = (float4*)(out + O4);
    if (c < 51) OP[a * 51 + c] = P[gidx * 51 + c];
    else        OV[a * 51 + (c - 51)] = V[gidx * 51 + (c - 51)];
}

extern "C" void kernel_launch(void* const* d_in, const int* in_sizes, int n_in,
                              void* d_out, int out_size) {
    const float* ps  = (const float*)d_in[0];  // pred_scores  (B,L,1)
    const float* pb  = (const float*)d_in[1];  // pred_bboxes  (B,L,4)
    const float* ap  = (const float*)d_in[2];  // anchor_points(L,2)
    const int*   gl  = (const int*)  d_in[3];  // gt_labels (all zero; defensive read)
    const float* gtb = (const float*)d_in[4];  // gt_bboxes    (B,n,4)
    const float* gp  = (const float*)d_in[5];  // gt_poses     (B,n,K,3)
    const float* gv  = (const float*)d_in[6];  // gt_vertices  (B,n,K,3)
    const float* gr  = (const float*)d_in[7];  // gt_rotations (B,n,3,3)
    const float* pad = (const float*)d_in[8];  // pad_gt_mask  (B,n,1)
    const int*   bg  = (const int*)  d_in[9];  // bg_index scalar
    float* out = (float*)d_out;

    k0_zero<<<528, 256>>>();
    k1_topk<<<BB * NG, 256>>>(ps, pb, ap, gtb, pad);
    dim3 g2((LL + 255) / 256, BB);
    k2_resolve<<<g2, 256>>>(ps, pb, gtb);
    k3_assign<<<g2, 256>>>(ps, pb, gtb, gr, gl, bg, out);
    // total float4 units = 16*8400*102 = 13,708,800 = 53550 * 256 exactly
    k4_copy<<<53550, 256>>>(gp, gv, out);
}

// round 4
// speedup vs baseline: 1.0773x; 1.0773x over previous
#include <cuda_runtime.h>
#include <cuda_bf16.h>

#define BB 16
#define LL 8400
#define NG 32
#define KK 68
#define NTOPK 13
#define EPSV 1e-9f
#define CAND_CAP 2048

// flat output offsets (float32 elements), tuple order:
// labels(B,L), bboxes(B,L,4), scores(B,L,1), poses(B,L,K,3), vertices(B,L,K,3),
// rotations(B,L,3,3), gt_index(B,L)
#define O1 134400
#define O2 672000
#define O3 806400
#define O4 28224000
#define O5 55641600
#define O6 56851200

// scratch (static __device__ globals — no runtime allocation)
__device__ unsigned int g_mask[BB * LL];   // per-anchor gt bitmask (initial mask_positive)
__device__ unsigned int g_final[BB * LL];  // after multi-claim resolution
__device__ int          g_gidx[BB * LL];   // flat assigned gt index
__device__ int          g_maxm[BB * NG];   // per-gt max metric   (float bits, >=0)
__device__ int          g_maxiou[BB * NG]; // per-gt max iou      (float bits, >=0)

__device__ __forceinline__ float iou_fn(float gx1, float gy1, float gx2, float gy2,
                                        float px1, float py1, float px2, float py2) {
    float ix1 = fmaxf(gx1, px1), iy1 = fmaxf(gy1, py1);
    float ix2 = fminf(gx2, px2), iy2 = fminf(gy2, py2);
    float ov = fmaxf(ix2 - ix1, 0.f) * fmaxf(iy2 - iy1, 0.f);
    float a1 = fmaxf(gx2 - gx1, 0.f) * fmaxf(gy2 - gy1, 0.f);
    float a2 = fmaxf(px2 - px1, 0.f) * fmaxf(py2 - py1, 0.f);
    return ov / (a1 + a2 - ov + EPSV);
}

__device__ __forceinline__ bool in_gts_fn(float ax, float ay, float4 g) {
    return (ax - g.x > EPSV) && (ay - g.y > EPSV) && (g.z - ax > EPSV) && (g.w - ay > EPSV);
}

// ---------------- K0: zero scratch ----------------
__global__ void k0_zero() {
    int idx = blockIdx.x * blockDim.x + threadIdx.x;
    int stride = gridDim.x * blockDim.x;
    for (int i = idx; i < BB * LL; i += stride) g_mask[i] = 0u;
    for (int i = idx; i < BB * NG; i += stride) { g_maxm[i] = 0; g_maxiou[i] = 0; }
}

// ---------------- K1: per (b,gt) top-13 via candidate compaction ----------------
// top_k input = alignment_metric * is_in_gts, so all non-in_gts entries are 0.
// Positive candidates (m>0 & in_gts) are sparse (~75-350 of 8400). Select top-13
// of those; if fewer than 13, lax.top_k fills with lowest-index zero entries
// (which set mask bits only when in_gts).
__global__ void k1_topk(const float* __restrict__ ps, const float* __restrict__ pb,
                        const float* __restrict__ ap, const float* __restrict__ gtb,
                        const float* __restrict__ pad) {
    __shared__ float cv[CAND_CAP];
    __shared__ int   ci[CAND_CAP];
    __shared__ int   cnt;
    int b  = blockIdx.x >> 5;
    int gi = blockIdx.x & 31;
    int t  = threadIdx.x;
    int gid = b * NG + gi;
    if (t == 0) cnt = 0;
    __syncthreads();
    float4 g = ((const float4*)gtb)[gid];
    float padv = pad[gid];
    const float* psb = ps + (size_t)b * LL;
    const float4* pbb = ((const float4*)pb) + (size_t)b * LL;

    // candidate compaction pass
    for (int l = t; l < LL; l += 256) {
        float ax = ap[2 * l], ay = ap[2 * l + 1];
        if (in_gts_fn(ax, ay, g)) {
            float4 p = pbb[l];
            float iou = iou_fn(g.x, g.y, g.z, g.w, p.x, p.y, p.z, p.w);
            float i2 = iou * iou;
            float m = psb[l] * (i2 * i2 * i2);
            if (m > 0.f) {
                int pos = atomicAdd(&cnt, 1);
                if (pos < CAND_CAP) { cv[pos] = m; ci[pos] = l; }
            }
        }
    }
    __syncthreads();
    if (padv == 0.f) return;  // topk_mask == 0 -> no positives from this gt
    int p = min(cnt, CAND_CAP);

    if (t < 32) {
        unsigned mbase = b * LL;
        int nsel = min(p, NTOPK);
        for (int k = 0; k < nsel; k++) {
            float bv = -1.f; int bi = 1 << 30; int bj = -1;
            for (int j = t; j < p; j += 32) {
                float v = cv[j]; int idx = ci[j];
                if (v > bv || (v == bv && idx < bi)) { bv = v; bi = idx; bj = j; }
            }
            #pragma unroll
            for (int off = 16; off > 0; off >>= 1) {
                float ov = __shfl_down_sync(0xffffffffu, bv, off);
                int oi = __shfl_down_sync(0xffffffffu, bi, off);
                int oj = __shfl_down_sync(0xffffffffu, bj, off);
                if (ov > bv || (ov == bv && oi < bi)) { bv = ov; bi = oi; bj = oj; }
            }
            bj = __shfl_sync(0xffffffffu, bj, 0);
            bi = __shfl_sync(0xffffffffu, bi, 0);
            if (t == 0) {
                cv[bj] = -1.f;  // remove from next rounds
                atomicOr(&g_mask[mbase + bi], 1u << gi);  // candidates are in_gts by construction
            }
            __syncwarp();
        }
        // fill remaining slots with lowest-index zero entries
        if (p < NTOPK && t == 0) {
            int need = NTOPK - p;
            for (int l = 0; need > 0 && l < LL; l++) {
                bool ispos = false;
                for (int j = 0; j < p; j++) if (ci[j] == l) { ispos = true; break; }
                if (!ispos) {
                    need--;
                    float ax = ap[2 * l], ay = ap[2 * l + 1];
                    if (in_gts_fn(ax, ay, g))
                        atomicOr(&g_mask[mbase + l], 1u << gi);
                }
            }
        }
    }
}

// ---------------- K2: resolve multi-claims, per-gt maxima, assigned gt index ----------------
__global__ void k2_resolve(const float* __restrict__ ps, const float* __restrict__ pb,
                           const float* __restrict__ gtb) {
    int b = blockIdx.y;
    int l = blockIdx.x * blockDim.x + threadIdx.x;
    __shared__ float4 sg[NG];
    if (threadIdx.x < NG) sg[threadIdx.x] = ((const float4*)gtb)[b * NG + threadIdx.x];
    __syncthreads();
    if (l >= LL) return;
    int a = b * LL + l;
    unsigned bits = g_mask[a];
    int cnt = __popc(bits);
    float4 p; float sc = 0.f;
    if (bits) { p = ((const float4*)pb)[a]; sc = ps[a]; }
    if (cnt > 1) {
        // replace column with one-hot argmax-iou over ALL gts (first-index tiebreak)
        float bv = -1.f; int bi = 0;
        #pragma unroll
        for (int i = 0; i < NG; i++) {
            float4 g = sg[i];
            float iou = iou_fn(g.x, g.y, g.z, g.w, p.x, p.y, p.z, p.w);
            if (iou > bv) { bv = iou; bi = i; }
        }
        bits = 1u << bi;
    }
    g_final[a] = bits;
    int i = bits ? (__ffs(bits) - 1) : 0;
    g_gidx[a] = b * NG + i;   // argmax of all-zero column = 0 (matches jnp.argmax)
    if (bits) {
        float4 g = sg[i];
        float iou = iou_fn(g.x, g.y, g.z, g.w, p.x, p.y, p.z, p.w);
        float i2 = iou * iou;
        float m = sc * (i2 * i2 * i2);
        atomicMax(&g_maxm[b * NG + i], __float_as_int(m));     // values >= 0: int order == float order
        atomicMax(&g_maxiou[b * NG + i], __float_as_int(iou));
    }
}

// ---------------- K34: all outputs, 112 units per anchor ----------------
// c in [0,51): poses float4 | [51,102): vertices float4 | [102,111): rotations scalar
// c == 111: labels + bboxes + scores + gt_index for this anchor
__global__ void k34_out(const float* __restrict__ ps, const float* __restrict__ pb,
                        const float* __restrict__ gtb, const float* __restrict__ gp,
                        const float* __restrict__ gv, const float* __restrict__ grot,
                        const int* __restrict__ gl, const int* __restrict__ bgp,
                        float* __restrict__ out) {
    unsigned t = blockIdx.x * 256u + threadIdx.x;
    unsigned a = t / 112u;
    int c = (int)(t - a * 112u);
    size_t gidx = (size_t)g_gidx[a];

    if (c < 102) {
        const float4* P = (const float4*)gp;
        const float4* V = (const float4*)gv;
        float4* OP = (float4*)(out + O3);
        float4* OV = (float4*)(out + O4);
        if (c < 51) OP[(size_t)a * 51 + c] = P[gidx * 51 + c];
        else        OV[(size_t)a * 51 + (c - 51)] = V[gidx * 51 + (c - 51)];
    } else if (c < 111) {
        int r = c - 102;
        out[O5 + (size_t)a * 9 + r] = grot[gidx * 9 + r];
    } else {
        unsigned bits = g_final[a];
        int lbl = bits ? gl[gidx] : bgp[0];
        float4 gbox = ((const float4*)gtb)[gidx];
        float score = 0.f;
        if (bits) {
            float4 p = ((const float4*)pb)[a];
            float iou = iou_fn(gbox.x, gbox.y, gbox.z, gbox.w, p.x, p.y, p.z, p.w);
            float i2 = iou * iou;
            float m = ps[a] * (i2 * i2 * i2);
            float mm = __int_as_float(g_maxm[gidx]);
            float mi = __int_as_float(g_maxiou[gidx]);
            float am = m / (mm + EPSV) * mi;
            score = (lbl == 0) ? am : 0.f;  // one_hot(lbl, C+1)[..., keep=[0]]
        }
        out[a] = (float)lbl;                // assigned_labels
        ((float4*)(out + O1))[a] = gbox;    // assigned_bboxes
        out[O2 + a] = score;                // assigned_scores
        out[O6 + a] = (float)gidx;          // assigned_gt_index
    }
}

extern "C" void kernel_launch(void* const* d_in, const int* in_sizes, int n_in,
                              void* d_out, int out_size) {
    const float* ps  = (const float*)d_in[0];  // pred_scores  (B,L,1)
    const float* pb  = (const float*)d_in[1];  // pred_bboxes  (B,L,4)
    const float* ap  = (const float*)d_in[2];  // anchor_points(L,2)
    const int*   gl  = (const int*)  d_in[3];  // gt_labels
    const float* gtb = (const float*)d_in[4];  // gt_bboxes    (B,n,4)
    const float* gp  = (const float*)d_in[5];  // gt_poses     (B,n,K,3)
    const float* gv  = (const float*)d_in[6];  // gt_vertices  (B,n,K,3)
    const float* gr  = (const float*)d_in[7];  // gt_rotations (B,n,3,3)
    const float* pad = (const float*)d_in[8];  // pad_gt_mask  (B,n,1)
    const int*   bg  = (const int*)  d_in[9];  // bg_index scalar
    float* out = (float*)d_out;

    k0_zero<<<528, 256>>>();
    k1_topk<<<BB * NG, 256>>>(ps, pb, ap, gtb, pad);
    dim3 g2((LL + 255) / 256, BB);
    k2_resolve<<<g2, 256>>>(ps, pb, gtb);
    // total units = 16*8400*112 = 15,052,800 = 58800 * 256 exactly
    k34_out<<<58800, 256>>>(ps, pb, gtb, gp, gv, gr, gl, bg, out);
}

// round 5
// speedup vs baseline: 1.5046x; 1.3967x over previous
#include <cuda_runtime.h>
#include <cuda_bf16.h>

#define BB 16
#define LL 8400
#define NG 32
#define KK 68
#define NTOPK 13
#define EPSV 1e-9f
#define CAND_CAP 2048

// flat output offsets (float32 elements), tuple order:
// labels(B,L), bboxes(B,L,4), scores(B,L,1), poses(B,L,K,3), vertices(B,L,K,3),
// rotations(B,L,3,3), gt_index(B,L)
#define O1 134400
#define O2 672000
#define O3 806400
#define O4 28224000
#define O5 55641600
#define O6 56851200

// scratch (static __device__ globals — no runtime allocation)
__device__ unsigned int g_mask[BB * LL];   // per-anchor gt bitmask (initial mask_positive)
__device__ unsigned int g_final[BB * LL];  // after multi-claim resolution
__device__ int          g_gidx[BB * LL];   // flat assigned gt index
__device__ int          g_maxm[BB * NG];   // per-gt max metric   (float bits, >=0)
__device__ int          g_maxiou[BB * NG]; // per-gt max iou      (float bits, >=0)

__device__ __forceinline__ float iou_fn(float gx1, float gy1, float gx2, float gy2,
                                        float px1, float py1, float px2, float py2) {
    float ix1 = fmaxf(gx1, px1), iy1 = fmaxf(gy1, py1);
    float ix2 = fminf(gx2, px2), iy2 = fminf(gy2, py2);
    float ov = fmaxf(ix2 - ix1, 0.f) * fmaxf(iy2 - iy1, 0.f);
    float a1 = fmaxf(gx2 - gx1, 0.f) * fmaxf(gy2 - gy1, 0.f);
    float a2 = fmaxf(px2 - px1, 0.f) * fmaxf(py2 - py1, 0.f);
    return ov / (a1 + a2 - ov + EPSV);
}

__device__ __forceinline__ bool in_gts_fn(float ax, float ay, float4 g) {
    return (ax - g.x > EPSV) && (ay - g.y > EPSV) && (g.z - ax > EPSV) && (g.w - ay > EPSV);
}

// ---------------- K0: zero scratch ----------------
__global__ void k0_zero() {
    int idx = blockIdx.x * blockDim.x + threadIdx.x;
    int stride = gridDim.x * blockDim.x;
    for (int i = idx; i < BB * LL; i += stride) g_mask[i] = 0u;
    for (int i = idx; i < BB * NG; i += stride) { g_maxm[i] = 0; g_maxiou[i] = 0; }
}

// ---------------- K1: per (b,gt) top-13 via candidate compaction ----------------
__global__ void k1_topk(const float* __restrict__ ps, const float* __restrict__ pb,
                        const float* __restrict__ ap, const float* __restrict__ gtb,
                        const float* __restrict__ pad) {
    __shared__ float cv[CAND_CAP];
    __shared__ int   ci[CAND_CAP];
    __shared__ int   cnt;
    int b  = blockIdx.x >> 5;
    int gi = blockIdx.x & 31;
    int t  = threadIdx.x;
    int gid = b * NG + gi;
    if (t == 0) cnt = 0;
    __syncthreads();
    float4 g = ((const float4*)gtb)[gid];
    float padv = pad[gid];
    const float* psb = ps + (size_t)b * LL;
    const float4* pbb = ((const float4*)pb) + (size_t)b * LL;

    // candidate compaction pass
    for (int l = t; l < LL; l += 256) {
        float ax = ap[2 * l], ay = ap[2 * l + 1];
        if (in_gts_fn(ax, ay, g)) {
            float4 p = pbb[l];
            float iou = iou_fn(g.x, g.y, g.z, g.w, p.x, p.y, p.z, p.w);
            float i2 = iou * iou;
            float m = psb[l] * (i2 * i2 * i2);
            if (m > 0.f) {
                int pos = atomicAdd(&cnt, 1);
                if (pos < CAND_CAP) { cv[pos] = m; ci[pos] = l; }
            }
        }
    }
    __syncthreads();
    if (padv == 0.f) return;  // topk_mask == 0 -> no positives from this gt
    int p = min(cnt, CAND_CAP);

    if (t < 32) {
        unsigned mbase = b * LL;
        int nsel = min(p, NTOPK);
        for (int k = 0; k < nsel; k++) {
            float bv = -1.f; int bi = 1 << 30; int bj = -1;
            for (int j = t; j < p; j += 32) {
                float v = cv[j]; int idx = ci[j];
                if (v > bv || (v == bv && idx < bi)) { bv = v; bi = idx; bj = j; }
            }
            #pragma unroll
            for (int off = 16; off > 0; off >>= 1) {
                float ov = __shfl_down_sync(0xffffffffu, bv, off);
                int oi = __shfl_down_sync(0xffffffffu, bi, off);
                int oj = __shfl_down_sync(0xffffffffu, bj, off);
                if (ov > bv || (ov == bv && oi < bi)) { bv = ov; bi = oi; bj = oj; }
            }
            bj = __shfl_sync(0xffffffffu, bj, 0);
            bi = __shfl_sync(0xffffffffu, bi, 0);
            if (t == 0) {
                cv[bj] = -1.f;  // remove from next rounds
                atomicOr(&g_mask[mbase + bi], 1u << gi);  // candidates are in_gts by construction
            }
            __syncwarp();
        }
        // fill remaining slots with lowest-index zero entries
        if (p < NTOPK && t == 0) {
            int need = NTOPK - p;
            for (int l = 0; need > 0 && l < LL; l++) {
                bool ispos = false;
                for (int j = 0; j < p; j++) if (ci[j] == l) { ispos = true; break; }
                if (!ispos) {
                    need--;
                    float ax = ap[2 * l], ay = ap[2 * l + 1];
                    if (in_gts_fn(ax, ay, g))
                        atomicOr(&g_mask[mbase + l], 1u << gi);
                }
            }
        }
    }
}

// ---------------- K2: resolve multi-claims, per-gt maxima, assigned gt index ----------------
__global__ void k2_resolve(const float* __restrict__ ps, const float* __restrict__ pb,
                           const float* __restrict__ gtb) {
    int b = blockIdx.y;
    int l = blockIdx.x * blockDim.x + threadIdx.x;
    __shared__ float4 sg[NG];
    if (threadIdx.x < NG) sg[threadIdx.x] = ((const float4*)gtb)[b * NG + threadIdx.x];
    __syncthreads();
    if (l >= LL) return;
    int a = b * LL + l;
    unsigned bits = g_mask[a];
    int cnt = __popc(bits);
    float4 p; float sc = 0.f;
    if (bits) { p = ((const float4*)pb)[a]; sc = ps[a]; }
    if (cnt > 1) {
        // replace column with one-hot argmax-iou over ALL gts (first-index tiebreak)
        float bv = -1.f; int bi = 0;
        #pragma unroll
        for (int i = 0; i < NG; i++) {
            float4 g = sg[i];
            float iou = iou_fn(g.x, g.y, g.z, g.w, p.x, p.y, p.z, p.w);
            if (iou > bv) { bv = iou; bi = i; }
        }
        bits = 1u << bi;
    }
    g_final[a] = bits;
    int i = bits ? (__ffs(bits) - 1) : 0;
    g_gidx[a] = b * NG + i;   // argmax of all-zero column = 0 (matches jnp.argmax)
    if (bits) {
        float4 g = sg[i];
        float iou = iou_fn(g.x, g.y, g.z, g.w, p.x, p.y, p.z, p.w);
        float i2 = iou * iou;
        float m = sc * (i2 * i2 * i2);
        atomicMax(&g_maxm[b * NG + i], __float_as_int(m));     // values >= 0: int order == float order
        atomicMax(&g_maxiou[b * NG + i], __float_as_int(iou));
    }
}

// ---------------- K34: warp-per-anchor, all outputs ----------------
// Each warp owns one anchor. Lanes batch 3-4 independent float4 load/stores
// (poses+vertices = 102 float4), lanes 0-8 copy rotations (coalesced 36B),
// lane 0 writes labels/bbox/score/gt_index.
__global__ void __launch_bounds__(256) k34_out(
        const float* __restrict__ ps, const float* __restrict__ pb,
        const float* __restrict__ gtb, const float* __restrict__ gp,
        const float* __restrict__ gv, const float* __restrict__ grot,
        const int* __restrict__ gl, const int* __restrict__ bgp,
        float* __restrict__ out) {
    unsigned a = (blockIdx.x * 256u + threadIdx.x) >> 5;   // anchor = warp id
    int lane = threadIdx.x & 31;
    size_t gidx = (size_t)g_gidx[a];

    const float4* Psrc = (const float4*)gp + gidx * 51;
    const float4* Vsrc = (const float4*)gv + gidx * 51;
    float4* Pd = (float4*)(out + O3) + (size_t)a * 51;
    float4* Vd = (float4*)(out + O4) + (size_t)a * 51;

    int c0 = lane, c1 = lane + 32, c2 = lane + 64, c3 = lane + 96;
    // batch independent loads (MLP ~3-4 per thread)
    float4 v0 = (c0 < 51) ? Psrc[c0] : Vsrc[c0 - 51];
    float4 v1 = (c1 < 51) ? Psrc[c1] : Vsrc[c1 - 51];
    float4 v2 = Vsrc[c2 - 51];                 // c2 in [64,96): always vertices
    float4 v3; bool has3 = (c3 < 102);
    float r9 = 0.f;
    if (has3) v3 = Vsrc[c3 - 51];
    if (lane < 9) r9 = grot[gidx * 9 + lane];

    if (c0 < 51) Pd[c0] = v0; else Vd[c0 - 51] = v0;
    if (c1 < 51) Pd[c1] = v1; else Vd[c1 - 51] = v1;
    Vd[c2 - 51] = v2;
    if (has3) Vd[c3 - 51] = v3;
    if (lane < 9) out[O5 + (size_t)a * 9 + lane] = r9;

    if (lane == 0) {
        unsigned bits = g_final[a];
        int lbl = bits ? gl[gidx] : bgp[0];
        float4 gbox = ((const float4*)gtb)[gidx];
        float score = 0.f;
        if (bits) {
            float4 p = ((const float4*)pb)[a];
            float iou = iou_fn(gbox.x, gbox.y, gbox.z, gbox.w, p.x, p.y, p.z, p.w);
            float i2 = iou * iou;
            float m = ps[a] * (i2 * i2 * i2);
            float mm = __int_as_float(g_maxm[gidx]);
            float mi = __int_as_float(g_maxiou[gidx]);
            float am = m / (mm + EPSV) * mi;
            score = (lbl == 0) ? am : 0.f;  // one_hot(lbl, C+1)[..., keep=[0]]
        }
        out[a] = (float)lbl;                // assigned_labels
        ((float4*)(out + O1))[a] = gbox;    // assigned_bboxes
        out[O2 + a] = score;                // assigned_scores
        out[O6 + a] = (float)gidx;          // assigned_gt_index
    }
}

extern "C" void kernel_launch(void* const* d_in, const int* in_sizes, int n_in,
                              void* d_out, int out_size) {
    const float* ps  = (const float*)d_in[0];  // pred_scores  (B,L,1)
    const float* pb  = (const float*)d_in[1];  // pred_bboxes  (B,L,4)
    const float* ap  = (const float*)d_in[2];  // anchor_points(L,2)
    const int*   gl  = (const int*)  d_in[3];  // gt_labels
    const float* gtb = (const float*)d_in[4];  // gt_bboxes    (B,n,4)
    const float* gp  = (const float*)d_in[5];  // gt_poses     (B,n,K,3)
    const float* gv  = (const float*)d_in[6];  // gt_vertices  (B,n,K,3)
    const float* gr  = (const float*)d_in[7];  // gt_rotations (B,n,3,3)
    const float* pad = (const float*)d_in[8];  // pad_gt_mask  (B,n,1)
    const int*   bg  = (const int*)  d_in[9];  // bg_index scalar
    float* out = (float*)d_out;

    k0_zero<<<528, 256>>>();
    k1_topk<<<BB * NG, 256>>>(ps, pb, ap, gtb, pad);
    dim3 g2((LL + 255) / 256, BB);
    k2_resolve<<<g2, 256>>>(ps, pb, gtb);
    // 134400 anchors = 134400 warps = 16800 blocks of 8 warps, exact
    k34_out<<<16800, 256>>>(ps, pb, gtb, gp, gv, gr, gl, bg, out);
}

// round 6
// speedup vs baseline: 1.6249x; 1.0800x over previous
#include <cuda_runtime.h>
#include <cuda_bf16.h>

#define BB 16
#define LL 8400
#define NG 32
#define KK 68
#define NTOPK 13
#define EPSV 1e-9f
#define CAND_CAP 1024
#define SEL_CAP 640

// flat output offsets (float32 elements), tuple order:
// labels(B,L), bboxes(B,L,4), scores(B,L,1), poses(B,L,K,3), vertices(B,L,K,3),
// rotations(B,L,3,3), gt_index(B,L)
#define O1 134400
#define O2 672000
#define O3 806400
#define O4 28224000
#define O5 55641600
#define O6 56851200

// scratch (static __device__ globals — no runtime allocation)
__device__ unsigned int g_mask[BB * LL];   // per-anchor gt bitmask (initial mask_positive)
__device__ unsigned int g_final[BB * LL];  // after multi-claim resolution
__device__ int          g_gidx[BB * LL];   // flat assigned gt index
__device__ int          g_maxm[BB * NG];   // per-gt max metric   (float bits, >=0)
__device__ int          g_maxiou[BB * NG]; // per-gt max iou      (float bits, >=0)
__device__ int          g_cnt[BB * NG];    // per-gt candidate count
__device__ float        g_cm[BB * NG * CAND_CAP]; // candidate metrics
__device__ int          g_ci[BB * NG * CAND_CAP]; // candidate anchor indices

__device__ __forceinline__ float iou_fn(float gx1, float gy1, float gx2, float gy2,
                                        float px1, float py1, float px2, float py2) {
    float ix1 = fmaxf(gx1, px1), iy1 = fmaxf(gy1, py1);
    float ix2 = fminf(gx2, px2), iy2 = fminf(gy2, py2);
    float ov = fmaxf(ix2 - ix1, 0.f) * fmaxf(iy2 - iy1, 0.f);
    float a1 = fmaxf(gx2 - gx1, 0.f) * fmaxf(gy2 - gy1, 0.f);
    float a2 = fmaxf(px2 - px1, 0.f) * fmaxf(py2 - py1, 0.f);
    return ov / (a1 + a2 - ov + EPSV);
}

__device__ __forceinline__ bool in_gts_fn(float ax, float ay, float4 g) {
    return (ax - g.x > EPSV) && (ay - g.y > EPSV) && (g.z - ax > EPSV) && (g.w - ay > EPSV);
}

// ---------------- K0: zero scratch ----------------
__global__ void k0_zero() {
    int idx = blockIdx.x * blockDim.x + threadIdx.x;
    int stride = gridDim.x * blockDim.x;
    for (int i = idx; i < BB * LL; i += stride) g_mask[i] = 0u;
    for (int i = idx; i < BB * NG; i += stride) { g_maxm[i] = 0; g_maxiou[i] = 0; g_cnt[i] = 0; }
}

// ---------------- K_cand: anchor-keyed candidate building ----------------
// Reads each anchor's pred box/score ONCE; appends (metric, l) to per-gt lists
// with warp-aggregated atomics. Candidate = in_gts && metric > 0.
__global__ void k_cand(const float* __restrict__ ps, const float* __restrict__ pb,
                       const float* __restrict__ ap, const float* __restrict__ gtb) {
    int b = blockIdx.y;
    int l = blockIdx.x * 256 + threadIdx.x;
    __shared__ float4 sg[NG];
    if (threadIdx.x < NG) sg[threadIdx.x] = ((const float4*)gtb)[b * NG + threadIdx.x];
    __syncthreads();
    bool act = (l < LL);
    int lane = threadIdx.x & 31;
    float ax = 0.f, ay = 0.f, sc = 0.f;
    float4 p = make_float4(0.f, 0.f, 0.f, 0.f);
    if (act) {
        float2 apv = ((const float2*)ap)[l];
        ax = apv.x; ay = apv.y;
        int a = b * LL + l;
        p = ((const float4*)pb)[a];
        sc = ps[a];
    }
    for (int i = 0; i < NG; i++) {
        float4 g = sg[i];
        float m = 0.f;
        if (act && in_gts_fn(ax, ay, g)) {
            float iou = iou_fn(g.x, g.y, g.z, g.w, p.x, p.y, p.z, p.w);
            float i2 = iou * iou;
            m = sc * (i2 * i2 * i2);
        }
        unsigned want = __ballot_sync(0xffffffffu, m > 0.f);
        if (want) {
            int gid = b * NG + i;
            int leader = __ffs(want) - 1;
            int base = 0;
            if (lane == leader) base = atomicAdd(&g_cnt[gid], __popc(want));
            base = __shfl_sync(0xffffffffu, base, leader);
            if (m > 0.f) {
                int pos = base + __popc(want & ((1u << lane) - 1u));
                if (pos < CAND_CAP) {
                    g_cm[gid * CAND_CAP + pos] = m;
                    g_ci[gid * CAND_CAP + pos] = l;
                }
            }
        }
    }
}

// ---------------- K_sel: warp-per-gt top-13 over candidate list ----------------
// Value+lowest-index tiebreak is order-invariant -> deterministic despite
// nondeterministic append order. If p<13, lax.top_k fills with lowest-index
// zero entries (set bit only when in_gts).
__global__ void __launch_bounds__(128) k_sel(const float* __restrict__ ap,
                                             const float* __restrict__ gtb,
                                             const float* __restrict__ pad) {
    __shared__ float sv[4][SEL_CAP];
    __shared__ int   si[4][SEL_CAP];
    int wl = threadIdx.x >> 5;
    int w  = blockIdx.x * 4 + wl;     // gt id: b*NG+gi
    int lane = threadIdx.x & 31;
    int b  = w >> 5;                  // NG == 32
    int gi = w & 31;
    if (pad[w] == 0.f) return;        // uniform over warp
    int p = min(g_cnt[w], SEL_CAP);
    int base = w * CAND_CAP;
    for (int j = lane; j < p; j += 32) { sv[wl][j] = g_cm[base + j]; si[wl][j] = g_ci[base + j]; }
    __syncwarp();
    unsigned mbase = b * LL;
    int nsel = min(p, NTOPK);
    for (int k = 0; k < nsel; k++) {
        float bv = -1.f; int bi = 1 << 30; int bj = -1;
        for (int j = lane; j < p; j += 32) {
            float v = sv[wl][j]; int idx = si[wl][j];
            if (v > bv || (v == bv && idx < bi)) { bv = v; bi = idx; bj = j; }
        }
        #pragma unroll
        for (int off = 16; off > 0; off >>= 1) {
            float ov = __shfl_down_sync(0xffffffffu, bv, off);
            int oi = __shfl_down_sync(0xffffffffu, bi, off);
            int oj = __shfl_down_sync(0xffffffffu, bj, off);
            if (ov > bv || (ov == bv && oi < bi)) { bv = ov; bi = oi; bj = oj; }
        }
        bj = __shfl_sync(0xffffffffu, bj, 0);
        bi = __shfl_sync(0xffffffffu, bi, 0);
        if (lane == 0) {
            sv[wl][bj] = -1.f;                        // remove selected
            atomicOr(&g_mask[mbase + bi], 1u << gi);  // candidates are in_gts by construction
        }
        __syncwarp();
    }
    if (p < NTOPK && lane == 0) {
        float4 g = ((const float4*)gtb)[w];
        int need = NTOPK - p;
        for (int l = 0; need > 0 && l < LL; l++) {
            bool ispos = false;
            for (int j = 0; j < p; j++) if (si[wl][j] == l) { ispos = true; break; }
            if (!ispos) {
                need--;
                float2 apv = ((const float2*)ap)[l];
                if (in_gts_fn(apv.x, apv.y, g))
                    atomicOr(&g_mask[mbase + l], 1u << gi);
            }
        }
    }
}

// ---------------- K2: resolve multi-claims, per-gt maxima, assigned gt index ----------------
__global__ void k2_resolve(const float* __restrict__ ps, const float* __restrict__ pb,
                           const float* __restrict__ gtb) {
    int b = blockIdx.y;
    int l = blockIdx.x * blockDim.x + threadIdx.x;
    __shared__ float4 sg[NG];
    if (threadIdx.x < NG) sg[threadIdx.x] = ((const float4*)gtb)[b * NG + threadIdx.x];
    __syncthreads();
    if (l >= LL) return;
    int a = b * LL + l;
    unsigned bits = g_mask[a];
    int cnt = __popc(bits);
    float4 p; float sc = 0.f;
    if (bits) { p = ((const float4*)pb)[a]; sc = ps[a]; }
    if (cnt > 1) {
        // replace column with one-hot argmax-iou over ALL gts (first-index tiebreak)
        float bv = -1.f; int bi = 0;
        #pragma unroll
        for (int i = 0; i < NG; i++) {
            float4 g = sg[i];
            float iou = iou_fn(g.x, g.y, g.z, g.w, p.x, p.y, p.z, p.w);
            if (iou > bv) { bv = iou; bi = i; }
        }
        bits = 1u << bi;
    }
    g_final[a] = bits;
    int i = bits ? (__ffs(bits) - 1) : 0;
    g_gidx[a] = b * NG + i;   // argmax of all-zero column = 0 (matches jnp.argmax)
    if (bits) {
        float4 g = sg[i];
        float iou = iou_fn(g.x, g.y, g.z, g.w, p.x, p.y, p.z, p.w);
        float i2 = iou * iou;
        float m = sc * (i2 * i2 * i2);
        atomicMax(&g_maxm[b * NG + i], __float_as_int(m));     // values >= 0: int order == float order
        atomicMax(&g_maxiou[b * NG + i], __float_as_int(iou));
    }
}

// ---------------- K34: warp-per-anchor, all outputs ----------------
__global__ void __launch_bounds__(256) k34_out(
        const float* __restrict__ ps, const float* __restrict__ pb,
        const float* __restrict__ gtb, const float* __restrict__ gp,
        const float* __restrict__ gv, const float* __restrict__ grot,
        const int* __restrict__ gl, const int* __restrict__ bgp,
        float* __restrict__ out) {
    unsigned a = (blockIdx.x * 256u + threadIdx.x) >> 5;   // anchor = warp id
    int lane = threadIdx.x & 31;
    size_t gidx = (size_t)g_gidx[a];

    const float4* Psrc = (const float4*)gp + gidx * 51;
    const float4* Vsrc = (const float4*)gv + gidx * 51;
    float4* Pd = (float4*)(out + O3) + (size_t)a * 51;
    float4* Vd = (float4*)(out + O4) + (size_t)a * 51;

    int c0 = lane, c1 = lane + 32, c2 = lane + 64, c3 = lane + 96;
    float4 v0 = (c0 < 51) ? Psrc[c0] : Vsrc[c0 - 51];
    float4 v1 = (c1 < 51) ? Psrc[c1] : Vsrc[c1 - 51];
    float4 v2 = Vsrc[c2 - 51];
    float4 v3; bool has3 = (c3 < 102);
    float r9 = 0.f;
    if (has3) v3 = Vsrc[c3 - 51];
    if (lane < 9) r9 = grot[gidx * 9 + lane];

    if (c0 < 51) Pd[c0] = v0; else Vd[c0 - 51] = v0;
    if (c1 < 51) Pd[c1] = v1; else Vd[c1 - 51] = v1;
    Vd[c2 - 51] = v2;
    if (has3) Vd[c3 - 51] = v3;
    if (lane < 9) out[O5 + (size_t)a * 9 + lane] = r9;

    if (lane == 0) {
        unsigned bits = g_final[a];
        int lbl = bits ? gl[gidx] : bgp[0];
        float4 gbox = ((const float4*)gtb)[gidx];
        float score = 0.f;
        if (bits) {
            float4 p = ((const float4*)pb)[a];
            float iou = iou_fn(gbox.x, gbox.y, gbox.z, gbox.w, p.x, p.y, p.z, p.w);
            float i2 = iou * iou;
            float m = ps[a] * (i2 * i2 * i2);
            float mm = __int_as_float(g_maxm[gidx]);
            float mi = __int_as_float(g_maxiou[gidx]);
            float am = m / (mm + EPSV) * mi;
            score = (lbl == 0) ? am : 0.f;  // one_hot(lbl, C+1)[..., keep=[0]]
        }
        out[a] = (float)lbl;                // assigned_labels
        ((float4*)(out + O1))[a] = gbox;    // assigned_bboxes
        out[O2 + a] = score;                // assigned_scores
        out[O6 + a] = (float)gidx;          // assigned_gt_index
    }
}

extern "C" void kernel_launch(void* const* d_in, const int* in_sizes, int n_in,
                              void* d_out, int out_size) {
    const float* ps  = (const float*)d_in[0];  // pred_scores  (B,L,1)
    const float* pb  = (const float*)d_in[1];  // pred_bboxes  (B,L,4)
    const float* ap  = (const float*)d_in[2];  // anchor_points(L,2)
    const int*   gl  = (const int*)  d_in[3];  // gt_labels
    const float* gtb = (const float*)d_in[4];  // gt_bboxes    (B,n,4)
    const float* gp  = (const float*)d_in[5];  // gt_poses     (B,n,K,3)
    const float* gv  = (const float*)d_in[6];  // gt_vertices  (B,n,K,3)
    const float* gr  = (const float*)d_in[7];  // gt_rotations (B,n,3,3)
    const float* pad = (const float*)d_in[8];  // pad_gt_mask  (B,n,1)
    const int*   bg  = (const int*)  d_in[9];  // bg_index scalar
    float* out = (float*)d_out;

    dim3 ga((LL + 255) / 256, BB);
    k0_zero<<<528, 256>>>();
    k_cand<<<ga, 256>>>(ps, pb, ap, gtb);
    k_sel<<<BB * NG / 4, 128>>>(ap, gtb, pad);
    k2_resolve<<<ga, 256>>>(ps, pb, gtb);
    // 134400 anchors = 134400 warps = 16800 blocks of 8 warps, exact
    k34_out<<<16800, 256>>>(ps, pb, gtb, gp, gv, gr, gl, bg, out);
}